// round 8
// baseline (speedup 1.0000x reference)
#include <cuda_runtime.h>
#include <cuda_bf16.h>
#include <cstdint>
#include <cstddef>

// Problem constants
#define L_DIM 9216          // 96*96
#define C_DIM 256
#define GW    96
#define NROWS (2 * L_DIM)   // B*L
// attn tiling
#define TM 128
#define TN 128
#define NT (L_DIM / TN)     // 72
#define NBUF 4

#define QSCALE 20.0f
// logits = dot_int / (QSCALE^2 * 16^3)
#define LSCALE (1.0f / (400.0f * 4096.0f))

// int8-quantized projected features (scratch)
__device__ __align__(128) uint8_t g_q0[NROWS * C_DIM];
__device__ __align__(128) uint8_t g_q1[NROWS * C_DIM];

typedef unsigned long long ull;

static __device__ __forceinline__ uint32_t smem_u32(const void* p) {
    return (uint32_t)__cvta_generic_to_shared(p);
}

// ---------------- f32x2 packed math ----------------
static __device__ __forceinline__ ull pk2(float a, float b) {
    ull r; asm("mov.b64 %0, {%1,%2};" : "=l"(r) : "f"(a), "f"(b)); return r;
}
static __device__ __forceinline__ void upk2(ull v, float& a, float& b) {
    asm("mov.b64 {%0,%1}, %2;" : "=f"(a), "=f"(b) : "l"(v));
}
static __device__ __forceinline__ ull fma2(ull a, ull b, ull c) {
    ull d; asm("fma.rn.f32x2 %0,%1,%2,%3;" : "=l"(d) : "l"(a), "l"(b), "l"(c)); return d;
}
static __device__ __forceinline__ ull add2(ull a, ull b) {
    ull d; asm("add.rn.f32x2 %0,%1,%2;" : "=l"(d) : "l"(a), "l"(b)); return d;
}

// ---------------- ldmatrix / mma ----------------
static __device__ __forceinline__ void ldmatrix_x4(uint32_t& r0, uint32_t& r1,
                                                   uint32_t& r2, uint32_t& r3,
                                                   uint32_t addr) {
    asm volatile("ldmatrix.sync.aligned.m8n8.x4.shared.b16 {%0,%1,%2,%3}, [%4];\n"
                 : "=r"(r0), "=r"(r1), "=r"(r2), "=r"(r3) : "r"(addr));
}
static __device__ __forceinline__ void mma16816(float* c, uint32_t a0, uint32_t a1,
                                                uint32_t a2, uint32_t a3, uint32_t b0,
                                                uint32_t b1) {
    asm volatile(
        "mma.sync.aligned.m16n8k16.row.col.f32.bf16.bf16.f32 "
        "{%0,%1,%2,%3}, {%4,%5,%6,%7}, {%8,%9}, {%0,%1,%2,%3};\n"
        : "+f"(c[0]), "+f"(c[1]), "+f"(c[2]), "+f"(c[3])
        : "r"(a0), "r"(a1), "r"(a2), "r"(a3), "r"(b0), "r"(b1));
}
static __device__ __forceinline__ void mma_s8(int* c, uint32_t a0, uint32_t a1,
                                              uint32_t a2, uint32_t a3, uint32_t b0,
                                              uint32_t b1) {
    asm volatile(
        "mma.sync.aligned.m16n8k32.row.col.s32.s8.s8.s32 "
        "{%0,%1,%2,%3}, {%4,%5,%6,%7}, {%8,%9}, {%0,%1,%2,%3};\n"
        : "+r"(c[0]), "+r"(c[1]), "+r"(c[2]), "+r"(c[3])
        : "r"(a0), "r"(a1), "r"(a2), "r"(a3), "r"(b0), "r"(b1));
}

// Swizzle for 512B rows (bf16 tiles)
static __device__ __forceinline__ int sw_off(int r, int c) {
    return r * 512 + (((c) ^ (r & 7)) << 4);
}
// Swizzle for 256B rows (int8 tiles): 16 chunks of 16B
static __device__ __forceinline__ int swb(int r, int c) {
    return r * 256 + ((c & 8) << 4) + (((c ^ r) & 7) << 4);
}

// ===========================================================================
// Projection kernel: f = feat @ W^T + b  (bf16 mma) -> int8 (x QSCALE)
// ===========================================================================
__global__ void __launch_bounds__(256) proj_kernel(const float* __restrict__ feat0,
                                                   const float* __restrict__ feat1,
                                                   const float* __restrict__ Wm,
                                                   const float* __restrict__ bias) {
    extern __shared__ char smem[];
    char* As = smem;            // 64 KB
    char* Ws = smem + 65536;    // 128 KB (all 256 rows of W)

    const int tid = threadIdx.x;
    const int warp = tid >> 5, lane = tid & 31;
    const bool is1 = (blockIdx.y != 0);
    const float* feat = is1 ? feat1 : feat0;
    uint8_t* outp = is1 ? g_q1 : g_q0;
    const int rowBase = blockIdx.x * 128;

    #pragma unroll
    for (int i = tid; i < 128 * 32; i += 256) {
        int r = i >> 5, c = i & 31;
        const float* src = feat + (size_t)(rowBase + r) * C_DIM + c * 8;
        float4 v0 = *(const float4*)(src);
        float4 v1 = *(const float4*)(src + 4);
        __nv_bfloat162 p0 = __floats2bfloat162_rn(v0.x, v0.y);
        __nv_bfloat162 p1 = __floats2bfloat162_rn(v0.z, v0.w);
        __nv_bfloat162 p2 = __floats2bfloat162_rn(v1.x, v1.y);
        __nv_bfloat162 p3 = __floats2bfloat162_rn(v1.z, v1.w);
        uint4 u;
        u.x = *(uint32_t*)&p0; u.y = *(uint32_t*)&p1;
        u.z = *(uint32_t*)&p2; u.w = *(uint32_t*)&p3;
        *(uint4*)(As + sw_off(r, c)) = u;
    }
    #pragma unroll
    for (int i = tid; i < 256 * 32; i += 256) {
        int r = i >> 5, c = i & 31;
        const float* src = Wm + (size_t)r * C_DIM + c * 8;
        float4 v0 = *(const float4*)(src);
        float4 v1 = *(const float4*)(src + 4);
        __nv_bfloat162 p0 = __floats2bfloat162_rn(v0.x, v0.y);
        __nv_bfloat162 p1 = __floats2bfloat162_rn(v0.z, v0.w);
        __nv_bfloat162 p2 = __floats2bfloat162_rn(v1.x, v1.y);
        __nv_bfloat162 p3 = __floats2bfloat162_rn(v1.z, v1.w);
        uint4 u;
        u.x = *(uint32_t*)&p0; u.y = *(uint32_t*)&p1;
        u.z = *(uint32_t*)&p2; u.w = *(uint32_t*)&p3;
        *(uint4*)(Ws + sw_off(r, c)) = u;
    }
    __syncthreads();

    uint32_t a[16][4];
    const int wr = warp * 16;
    const int aR = wr + (lane & 7) + (lane & 8);
    const uint32_t aRowBase = smem_u32(As) + aR * 512;
    const int aXor = aR & 7;
    #pragma unroll
    for (int kk = 0; kk < 16; kk++) {
        int chunk = kk * 2 + (lane >> 4);
        ldmatrix_x4(a[kk][0], a[kk][1], a[kk][2], a[kk][3],
                    aRowBase + ((chunk ^ aXor) << 4));
    }

    const int bR = (lane & 7) + ((lane & 16) >> 1);
    const int bChunkOff = (lane >> 3) & 1;
    const uint32_t wsBase = smem_u32(Ws);

    #pragma unroll 1
    for (int nt = 0; nt < 4; nt++) {
        float acc[8][4];
        #pragma unroll
        for (int j = 0; j < 8; j++)
            #pragma unroll
            for (int q = 0; q < 4; q++) acc[j][q] = 0.0f;

        #pragma unroll
        for (int kk = 0; kk < 16; kk++) {
            #pragma unroll
            for (int jp = 0; jp < 4; jp++) {
                int R = nt * 64 + jp * 16 + bR;
                uint32_t addr = wsBase + R * 512 +
                                (((kk * 2 + bChunkOff) ^ (R & 7)) << 4);
                uint32_t b0, b1, b2, b3;
                ldmatrix_x4(b0, b1, b2, b3, addr);
                mma16816(acc[jp * 2],     a[kk][0], a[kk][1], a[kk][2], a[kk][3], b0, b1);
                mma16816(acc[jp * 2 + 1], a[kk][0], a[kk][1], a[kk][2], a[kk][3], b2, b3);
            }
        }

        int r0 = rowBase + wr + (lane >> 2);
        #pragma unroll
        for (int j = 0; j < 8; j++) {
            int col = nt * 64 + j * 8 + 2 * (lane & 3);
            float bb0 = bias[col], bb1 = bias[col + 1];
            int i0 = __float2int_rn(fminf(fmaxf((acc[j][0] + bb0) * QSCALE, -127.f), 127.f));
            int i1 = __float2int_rn(fminf(fmaxf((acc[j][1] + bb1) * QSCALE, -127.f), 127.f));
            int i2 = __float2int_rn(fminf(fmaxf((acc[j][2] + bb0) * QSCALE, -127.f), 127.f));
            int i3 = __float2int_rn(fminf(fmaxf((acc[j][3] + bb1) * QSCALE, -127.f), 127.f));
            uint16_t lo = (uint16_t)((i0 & 0xff) | ((i1 & 0xff) << 8));
            uint16_t hi = (uint16_t)((i2 & 0xff) | ((i3 & 0xff) << 8));
            *(uint16_t*)(outp + (size_t)r0 * C_DIM + col) = lo;
            *(uint16_t*)(outp + (size_t)(r0 + 8) * C_DIM + col) = hi;
        }
    }
}

// ===========================================================================
// Attention kernel: int8 mma, 256 threads, warp tile M=32 x N=64,
// software-pipelined MMA/EPI per 16-col group:
//   MMA(0) MMA(1) EPI(0) MMA(2) EPI(1) MMA(3) EPI(2) EPI(3)
// ===========================================================================
#define SM_A 0
#define SM_B 32768
#define SM_PART (32768 + NBUF * 32768)              // 163840
#define SM_TOTAL (SM_PART + 2 * 128 * 3 * 4)        // +3072

__global__ void __launch_bounds__(256, 1) attn_kernel(float* __restrict__ out) {
    extern __shared__ char smem[];
    const uint32_t sbase = smem_u32(smem);
    const int tid = threadIdx.x;
    const int warp = tid >> 5, lane = tid & 31;
    const int g = warp >> 1;      // row group 0..3 (32 rows each)
    const int h = warp & 1;       // col half 0..1
    const int bat = blockIdx.y;
    const uint8_t* f0 = g_q0 + (size_t)bat * L_DIM * C_DIM;
    const uint8_t* f1 = g_q1 + (size_t)bat * L_DIM * C_DIM;
    const int rowBase = blockIdx.x * TM;

    auto loadB = [&](int t) {
        const uint8_t* src = f1 + (size_t)t * TN * C_DIM;
        uint32_t Bb = sbase + SM_B + (uint32_t)(t & (NBUF - 1)) * 32768u;
        #pragma unroll
        for (int k = 0; k < 8; k++) {
            int i = k * 256 + tid;
            int r = i >> 4, c = i & 15;
            uint32_t dst = Bb + swb(r, c);
            const void* gp = (const void*)(src + r * C_DIM + c * 16);
            asm volatile("cp.async.cg.shared.global [%0], [%1], 16;\n" ::"r"(dst), "l"(gp));
        }
        asm volatile("cp.async.commit_group;\n" ::);
    };

    // Prologue
    #pragma unroll
    for (int k = 0; k < 8; k++) {
        int i = k * 256 + tid;
        int r = i >> 4, c = i & 15;
        uint32_t dst = sbase + SM_A + swb(r, c);
        const void* gp = (const void*)(f0 + (size_t)(rowBase + r) * C_DIM + c * 16);
        asm volatile("cp.async.cg.shared.global [%0], [%1], 16;\n" ::"r"(dst), "l"(gp));
    }
    loadB(0);
    loadB(1);
    loadB(2);

    asm volatile("cp.async.wait_group 2;\n" ::);  // A + B0 resident
    __syncthreads();

    // Hoist A fragments: 8 k-steps x 2 m-groups x 4 regs (rows g*32..+32)
    uint32_t a[8][2][4];
    const int wr = g * 32;
    #pragma unroll
    for (int m = 0; m < 2; m++) {
        const int aR = wr + m * 16 + (lane & 7) + (lane & 8);
        const uint32_t aRowBase = sbase + SM_A + aR * 256;
        #pragma unroll
        for (int kk = 0; kk < 8; kk++) {
            int c = kk * 2 + (lane >> 4);
            ldmatrix_x4(a[kk][m][0], a[kk][m][1], a[kk][m][2], a[kk][m][3],
                        aRowBase + ((c & 8) << 4) + (((c ^ aR) & 7) << 4));
        }
    }

    // B ldmatrix addressing: hoist swizzle offsets (lane-constant)
    const int bRlo = (lane & 7) + ((lane >> 4) << 3);
    const int bCk = (lane >> 3) & 1;
    const int r7 = bRlo & 7;
    uint32_t offk[8];
    #pragma unroll
    for (int kk = 0; kk < 8; kk++) {
        int c = kk * 2 + bCk;
        offk[kk] = (uint32_t)(((c & 8) << 4) + (((c ^ r7) & 7) << 4));
    }
    const uint32_t bRowOff = (uint32_t)((h * 64 + bRlo) * 256);

    // exp(LSCALE * v) Taylor coefficients (packed)
    const float s1 = LSCALE;
    const float s2 = 0.5f * s1 * s1;
    const float s3 = (1.0f / 6.0f) * s1 * s1 * s1;
    const float s4 = (1.0f / 24.0f) * s1 * s1 * s1 * s1;
    const ull C4 = pk2(s4, s4), C3 = pk2(s3, s3), C2 = pk2(s2, s2);
    const ull C1 = pk2(s1, s1), CONE = pk2(1.0f, 1.0f);

    // E/X/Y accumulators for 4 row-subsets (m-group x {r, r+8})
    ull E[2][2], X[2][2], Y[2][2];
    #pragma unroll
    for (int m = 0; m < 2; m++)
        #pragma unroll
        for (int q = 0; q < 2; q++) {
            E[m][q] = pk2(0.f, 0.f); X[m][q] = E[m][q]; Y[m][q] = E[m][q];
        }

    const int sl_base = h * 64 + 2 * (lane & 3);

    for (int t = 0; t < NT; t++) {
        if (t > 0) {
            asm volatile("cp.async.wait_group 2;\n" ::);
            __syncthreads();
        }
        if (t + 3 < NT) loadB(t + 3);
        else asm volatile("cp.async.commit_group;\n" ::);

        const uint32_t Bbase = sbase + SM_B + (uint32_t)(t & (NBUF - 1)) * 32768u + bRowOff;

        // Tile-dependent coordinate constants
        const int scol = t * TN;
        const int y0 = scol / GW;
        const int x0 = scol - y0 * GW;
        const int wrp = GW - x0;
        const float y0f = (float)y0, y1f = y0f + 1.f;
        const float xa = (float)x0, xb = (float)(x0 - GW);

        // 4 independent accumulator sets (one per 16-col group)
        int acc[4][2][2][4];

        // --- MMA block for column group jp ---
        auto MMAJ = [&](int jp) {
            #pragma unroll
            for (int m = 0; m < 2; m++)
                #pragma unroll
                for (int s = 0; s < 2; s++)
                    #pragma unroll
                    for (int q = 0; q < 4; q++) acc[jp][m][s][q] = 0;
            #pragma unroll
            for (int kk = 0; kk < 8; kk++) {
                uint32_t addr = Bbase + jp * 4096 + offk[kk];
                uint32_t b0, b1, b2, b3;
                ldmatrix_x4(b0, b1, b2, b3, addr);
                mma_s8(acc[jp][0][0], a[kk][0][0], a[kk][0][1], a[kk][0][2], a[kk][0][3], b0, b1);
                mma_s8(acc[jp][0][1], a[kk][0][0], a[kk][0][1], a[kk][0][2], a[kk][0][3], b2, b3);
                mma_s8(acc[jp][1][0], a[kk][1][0], a[kk][1][1], a[kk][1][2], a[kk][1][3], b0, b1);
                mma_s8(acc[jp][1][1], a[kk][1][0], a[kk][1][1], a[kk][1][2], a[kk][1][3], b2, b3);
            }
        };

        // --- Epilogue for column group jp ---
        auto EPIJ = [&](int jp) {
            #pragma unroll
            for (int s = 0; s < 2; s++) {
                int j = jp * 2 + s;
                int sl0 = j * 8 + sl_base, sl1 = sl0 + 1;
                bool p0 = sl0 >= wrp, p1 = sl1 >= wrp;
                ull xp = pk2((p0 ? xb : xa) + (float)sl0, (p1 ? xb : xa) + (float)sl1);
                ull yp = pk2(p0 ? y1f : y0f, p1 ? y1f : y0f);
                #pragma unroll
                for (int m = 0; m < 2; m++) {
                    ull vlo = pk2(__int2float_rn(acc[jp][m][s][0]),
                                  __int2float_rn(acc[jp][m][s][1]));
                    ull vhi = pk2(__int2float_rn(acc[jp][m][s][2]),
                                  __int2float_rn(acc[jp][m][s][3]));

                    ull e = fma2(vlo, C4, C3);
                    e = fma2(vlo, e, C2);
                    e = fma2(vlo, e, C1);
                    e = fma2(vlo, e, CONE);
                    E[m][0] = add2(E[m][0], e);
                    X[m][0] = fma2(e, xp, X[m][0]);
                    Y[m][0] = fma2(e, yp, Y[m][0]);

                    ull f = fma2(vhi, C4, C3);
                    f = fma2(vhi, f, C2);
                    f = fma2(vhi, f, C1);
                    f = fma2(vhi, f, CONE);
                    E[m][1] = add2(E[m][1], f);
                    X[m][1] = fma2(f, xp, X[m][1]);
                    Y[m][1] = fma2(f, yp, Y[m][1]);
                }
            }
        };

        // Software-pipelined issue order: EPI(jp) overlaps MMA(jp+1)
        MMAJ(0);
        MMAJ(1);
        EPIJ(0);
        MMAJ(2);
        EPIJ(1);
        MMAJ(3);
        EPIJ(2);
        EPIJ(3);
    }

    // Fold packed halves, reduce across lane quads, publish per-half partials
    float* part = (float*)(smem + SM_PART);
    #pragma unroll
    for (int m = 0; m < 2; m++) {
        #pragma unroll
        for (int q = 0; q < 2; q++) {
            float ea, eb, xa2, xb2, ya, yb;
            upk2(E[m][q], ea, eb); upk2(X[m][q], xa2, xb2); upk2(Y[m][q], ya, yb);
            float sE = ea + eb, sX = xa2 + xb2, sY = ya + yb;
            #pragma unroll
            for (int off = 1; off < 4; off <<= 1) {
                sE += __shfl_xor_sync(0xffffffffu, sE, off);
                sX += __shfl_xor_sync(0xffffffffu, sX, off);
                sY += __shfl_xor_sync(0xffffffffu, sY, off);
            }
            if ((lane & 3) == 0) {
                int row = wr + m * 16 + q * 8 + (lane >> 2);
                float* pp = part + (size_t)(h * 128 + row) * 3;
                pp[0] = sE; pp[1] = sX; pp[2] = sY;
            }
        }
    }
    __syncthreads();

    if (tid < 128) {
        const int row = tid;
        float sE = part[row * 3 + 0] + part[(128 + row) * 3 + 0];
        float sX = part[row * 3 + 1] + part[(128 + row) * 3 + 1];
        float sY = part[row * 3 + 2] + part[(128 + row) * 3 + 2];
        const int lq = rowBase + row;
        const int xq = lq % GW, yq = lq / GW;
        const bool border = (xq < 2) | (xq >= GW - 2) | (yq < 2) | (yq >= GW - 2);
        const float inv = 1.0f / sE;
        float* outb = out + (size_t)bat * 2 * L_DIM;
        outb[lq] = border ? 0.0f : (sX * inv - (float)xq);
        outb[L_DIM + lq] = border ? 0.0f : (sY * inv - (float)yq);
    }
}

// ---------------------------------------------------------------------------
extern "C" void kernel_launch(void* const* d_in, const int* in_sizes, int n_in,
                              void* d_out, int out_size) {
    (void)in_sizes; (void)n_in; (void)out_size;
    const float* feat0 = (const float*)d_in[0];
    const float* feat1 = (const float*)d_in[1];
    const float* Wm    = (const float*)d_in[2];
    const float* bias  = (const float*)d_in[3];
    float* out = (float*)d_out;

    cudaFuncSetAttribute(proj_kernel, cudaFuncAttributeMaxDynamicSharedMemorySize, 196608);
    cudaFuncSetAttribute(attn_kernel, cudaFuncAttributeMaxDynamicSharedMemorySize, SM_TOTAL);

    proj_kernel<<<dim3(NROWS / 128, 2), 256, 196608>>>(feat0, feat1, Wm, bias);
    attn_kernel<<<dim3(L_DIM / TM, 2), 256, SM_TOTAL>>>(out);
}

// round 9
// speedup vs baseline: 1.0398x; 1.0398x over previous
#include <cuda_runtime.h>
#include <cuda_bf16.h>
#include <cstdint>
#include <cstddef>

// Problem constants
#define L_DIM 9216          // 96*96
#define C_DIM 256
#define GW    96
#define NROWS (2 * L_DIM)   // B*L
// attn tiling
#define TM 128
#define TN 128
#define NT (L_DIM / TN)     // 72
#define NBUF 4

#define QSCALE 20.0f
// logits = dot_int / (QSCALE^2 * 16^3)
#define LSCALE (1.0f / (400.0f * 4096.0f))

// int8-quantized projected features (scratch)
__device__ __align__(128) uint8_t g_q0[NROWS * C_DIM];
__device__ __align__(128) uint8_t g_q1[NROWS * C_DIM];

typedef unsigned long long ull;

static __device__ __forceinline__ uint32_t smem_u32(const void* p) {
    return (uint32_t)__cvta_generic_to_shared(p);
}

// ---------------- f32x2 packed math ----------------
static __device__ __forceinline__ ull pk2(float a, float b) {
    ull r; asm("mov.b64 %0, {%1,%2};" : "=l"(r) : "f"(a), "f"(b)); return r;
}
static __device__ __forceinline__ void upk2(ull v, float& a, float& b) {
    asm("mov.b64 {%0,%1}, %2;" : "=f"(a), "=f"(b) : "l"(v));
}
static __device__ __forceinline__ ull fma2(ull a, ull b, ull c) {
    ull d; asm("fma.rn.f32x2 %0,%1,%2,%3;" : "=l"(d) : "l"(a), "l"(b), "l"(c)); return d;
}
static __device__ __forceinline__ ull add2(ull a, ull b) {
    ull d; asm("add.rn.f32x2 %0,%1,%2;" : "=l"(d) : "l"(a), "l"(b)); return d;
}

// ---------------- ldmatrix / mma ----------------
static __device__ __forceinline__ void ldmatrix_x4(uint32_t& r0, uint32_t& r1,
                                                   uint32_t& r2, uint32_t& r3,
                                                   uint32_t addr) {
    asm volatile("ldmatrix.sync.aligned.m8n8.x4.shared.b16 {%0,%1,%2,%3}, [%4];\n"
                 : "=r"(r0), "=r"(r1), "=r"(r2), "=r"(r3) : "r"(addr));
}
static __device__ __forceinline__ void mma16816(float* c, uint32_t a0, uint32_t a1,
                                                uint32_t a2, uint32_t a3, uint32_t b0,
                                                uint32_t b1) {
    asm volatile(
        "mma.sync.aligned.m16n8k16.row.col.f32.bf16.bf16.f32 "
        "{%0,%1,%2,%3}, {%4,%5,%6,%7}, {%8,%9}, {%0,%1,%2,%3};\n"
        : "+f"(c[0]), "+f"(c[1]), "+f"(c[2]), "+f"(c[3])
        : "r"(a0), "r"(a1), "r"(a2), "r"(a3), "r"(b0), "r"(b1));
}
static __device__ __forceinline__ void mma_s8(int* c, uint32_t a0, uint32_t a1,
                                              uint32_t a2, uint32_t a3, uint32_t b0,
                                              uint32_t b1) {
    asm volatile(
        "mma.sync.aligned.m16n8k32.row.col.s32.s8.s8.s32 "
        "{%0,%1,%2,%3}, {%4,%5,%6,%7}, {%8,%9}, {%0,%1,%2,%3};\n"
        : "+r"(c[0]), "+r"(c[1]), "+r"(c[2]), "+r"(c[3])
        : "r"(a0), "r"(a1), "r"(a2), "r"(a3), "r"(b0), "r"(b1));
}

// Swizzle for 512B rows (bf16 tiles)
static __device__ __forceinline__ int sw_off(int r, int c) {
    return r * 512 + (((c) ^ (r & 7)) << 4);
}
// Swizzle for 256B rows (int8 tiles): 16 chunks of 16B
static __device__ __forceinline__ int swb(int r, int c) {
    return r * 256 + ((c & 8) << 4) + (((c ^ r) & 7) << 4);
}

// ===========================================================================
// Projection kernel: f = feat @ W^T + b  (bf16 mma) -> int8 (x QSCALE)
// ===========================================================================
__global__ void __launch_bounds__(256) proj_kernel(const float* __restrict__ feat0,
                                                   const float* __restrict__ feat1,
                                                   const float* __restrict__ Wm,
                                                   const float* __restrict__ bias) {
    extern __shared__ char smem[];
    char* As = smem;            // 64 KB
    char* Ws = smem + 65536;    // 128 KB (all 256 rows of W)

    const int tid = threadIdx.x;
    const int warp = tid >> 5, lane = tid & 31;
    const bool is1 = (blockIdx.y != 0);
    const float* feat = is1 ? feat1 : feat0;
    uint8_t* outp = is1 ? g_q1 : g_q0;
    const int rowBase = blockIdx.x * 128;

    #pragma unroll
    for (int i = tid; i < 128 * 32; i += 256) {
        int r = i >> 5, c = i & 31;
        const float* src = feat + (size_t)(rowBase + r) * C_DIM + c * 8;
        float4 v0 = *(const float4*)(src);
        float4 v1 = *(const float4*)(src + 4);
        __nv_bfloat162 p0 = __floats2bfloat162_rn(v0.x, v0.y);
        __nv_bfloat162 p1 = __floats2bfloat162_rn(v0.z, v0.w);
        __nv_bfloat162 p2 = __floats2bfloat162_rn(v1.x, v1.y);
        __nv_bfloat162 p3 = __floats2bfloat162_rn(v1.z, v1.w);
        uint4 u;
        u.x = *(uint32_t*)&p0; u.y = *(uint32_t*)&p1;
        u.z = *(uint32_t*)&p2; u.w = *(uint32_t*)&p3;
        *(uint4*)(As + sw_off(r, c)) = u;
    }
    #pragma unroll
    for (int i = tid; i < 256 * 32; i += 256) {
        int r = i >> 5, c = i & 31;
        const float* src = Wm + (size_t)r * C_DIM + c * 8;
        float4 v0 = *(const float4*)(src);
        float4 v1 = *(const float4*)(src + 4);
        __nv_bfloat162 p0 = __floats2bfloat162_rn(v0.x, v0.y);
        __nv_bfloat162 p1 = __floats2bfloat162_rn(v0.z, v0.w);
        __nv_bfloat162 p2 = __floats2bfloat162_rn(v1.x, v1.y);
        __nv_bfloat162 p3 = __floats2bfloat162_rn(v1.z, v1.w);
        uint4 u;
        u.x = *(uint32_t*)&p0; u.y = *(uint32_t*)&p1;
        u.z = *(uint32_t*)&p2; u.w = *(uint32_t*)&p3;
        *(uint4*)(Ws + sw_off(r, c)) = u;
    }
    __syncthreads();

    uint32_t a[16][4];
    const int wr = warp * 16;
    const int aR = wr + (lane & 7) + (lane & 8);
    const uint32_t aRowBase = smem_u32(As) + aR * 512;
    const int aXor = aR & 7;
    #pragma unroll
    for (int kk = 0; kk < 16; kk++) {
        int chunk = kk * 2 + (lane >> 4);
        ldmatrix_x4(a[kk][0], a[kk][1], a[kk][2], a[kk][3],
                    aRowBase + ((chunk ^ aXor) << 4));
    }

    const int bR = (lane & 7) + ((lane & 16) >> 1);
    const int bChunkOff = (lane >> 3) & 1;
    const uint32_t wsBase = smem_u32(Ws);

    #pragma unroll 1
    for (int nt = 0; nt < 4; nt++) {
        float acc[8][4];
        #pragma unroll
        for (int j = 0; j < 8; j++)
            #pragma unroll
            for (int q = 0; q < 4; q++) acc[j][q] = 0.0f;

        #pragma unroll
        for (int kk = 0; kk < 16; kk++) {
            #pragma unroll
            for (int jp = 0; jp < 4; jp++) {
                int R = nt * 64 + jp * 16 + bR;
                uint32_t addr = wsBase + R * 512 +
                                (((kk * 2 + bChunkOff) ^ (R & 7)) << 4);
                uint32_t b0, b1, b2, b3;
                ldmatrix_x4(b0, b1, b2, b3, addr);
                mma16816(acc[jp * 2],     a[kk][0], a[kk][1], a[kk][2], a[kk][3], b0, b1);
                mma16816(acc[jp * 2 + 1], a[kk][0], a[kk][1], a[kk][2], a[kk][3], b2, b3);
            }
        }

        int r0 = rowBase + wr + (lane >> 2);
        #pragma unroll
        for (int j = 0; j < 8; j++) {
            int col = nt * 64 + j * 8 + 2 * (lane & 3);
            float bb0 = bias[col], bb1 = bias[col + 1];
            int i0 = __float2int_rn(fminf(fmaxf((acc[j][0] + bb0) * QSCALE, -127.f), 127.f));
            int i1 = __float2int_rn(fminf(fmaxf((acc[j][1] + bb1) * QSCALE, -127.f), 127.f));
            int i2 = __float2int_rn(fminf(fmaxf((acc[j][2] + bb0) * QSCALE, -127.f), 127.f));
            int i3 = __float2int_rn(fminf(fmaxf((acc[j][3] + bb1) * QSCALE, -127.f), 127.f));
            uint16_t lo = (uint16_t)((i0 & 0xff) | ((i1 & 0xff) << 8));
            uint16_t hi = (uint16_t)((i2 & 0xff) | ((i3 & 0xff) << 8));
            *(uint16_t*)(outp + (size_t)r0 * C_DIM + col) = lo;
            *(uint16_t*)(outp + (size_t)(r0 + 8) * C_DIM + col) = hi;
        }
    }
}

// ===========================================================================
// Attention kernel: int8 mma, 256 threads, warp tile M=32 x N=64.
// Cross-tile software pipeline at 16-col-group (jp) granularity:
//   iteration t:  EPI_t(jp) ; MMA_{t+1}(jp)   for jp = 0..3
// EPI reads accumulators produced a full tile earlier (retired), so its
// FMA/ALU stream fills the issue slots the QMMA stream leaves open.
// ===========================================================================
#define SM_A 0
#define SM_B 32768
#define SM_PART (32768 + NBUF * 32768)              // 163840
#define SM_TOTAL (SM_PART + 2 * 128 * 3 * 4)        // +3072

__global__ void __launch_bounds__(256, 1) attn_kernel(float* __restrict__ out) {
    extern __shared__ char smem[];
    const uint32_t sbase = smem_u32(smem);
    const int tid = threadIdx.x;
    const int warp = tid >> 5, lane = tid & 31;
    const int g = warp >> 1;      // row group 0..3 (32 rows each)
    const int h = warp & 1;       // col half 0..1
    const int bat = blockIdx.y;
    const uint8_t* f0 = g_q0 + (size_t)bat * L_DIM * C_DIM;
    const uint8_t* f1 = g_q1 + (size_t)bat * L_DIM * C_DIM;
    const int rowBase = blockIdx.x * TM;

    auto loadB = [&](int t) {
        const uint8_t* src = f1 + (size_t)t * TN * C_DIM;
        uint32_t Bb = sbase + SM_B + (uint32_t)(t & (NBUF - 1)) * 32768u;
        #pragma unroll
        for (int k = 0; k < 8; k++) {
            int i = k * 256 + tid;
            int r = i >> 4, c = i & 15;
            uint32_t dst = Bb + swb(r, c);
            const void* gp = (const void*)(src + r * C_DIM + c * 16);
            asm volatile("cp.async.cg.shared.global [%0], [%1], 16;\n" ::"r"(dst), "l"(gp));
        }
        asm volatile("cp.async.commit_group;\n" ::);
    };

    // Prologue: group0 = A tile + B0; groups 1,2 = B1,B2
    #pragma unroll
    for (int k = 0; k < 8; k++) {
        int i = k * 256 + tid;
        int r = i >> 4, c = i & 15;
        uint32_t dst = sbase + SM_A + swb(r, c);
        const void* gp = (const void*)(f0 + (size_t)(rowBase + r) * C_DIM + c * 16);
        asm volatile("cp.async.cg.shared.global [%0], [%1], 16;\n" ::"r"(dst), "l"(gp));
    }
    loadB(0);
    loadB(1);
    loadB(2);

    asm volatile("cp.async.wait_group 2;\n" ::);  // A + B0 resident
    __syncthreads();

    // Hoist A fragments: 8 k-steps x 2 m-groups x 4 regs (rows g*32..+32)
    uint32_t a[8][2][4];
    const int wr = g * 32;
    #pragma unroll
    for (int m = 0; m < 2; m++) {
        const int aR = wr + m * 16 + (lane & 7) + (lane & 8);
        const uint32_t aRowBase = sbase + SM_A + aR * 256;
        #pragma unroll
        for (int kk = 0; kk < 8; kk++) {
            int c = kk * 2 + (lane >> 4);
            ldmatrix_x4(a[kk][m][0], a[kk][m][1], a[kk][m][2], a[kk][m][3],
                        aRowBase + ((c & 8) << 4) + (((c ^ aR) & 7) << 4));
        }
    }

    // B ldmatrix addressing: hoist swizzle offsets (lane-constant)
    const int bRlo = (lane & 7) + ((lane >> 4) << 3);
    const int bCk = (lane >> 3) & 1;
    const int r7 = bRlo & 7;
    uint32_t offk[8];
    #pragma unroll
    for (int kk = 0; kk < 8; kk++) {
        int c = kk * 2 + bCk;
        offk[kk] = (uint32_t)(((c & 8) << 4) + (((c ^ r7) & 7) << 4));
    }
    const uint32_t bRowOff = (uint32_t)((h * 64 + bRlo) * 256);

    // exp(LSCALE * v), degree-3 Taylor (|LSCALE*v| <= ~0.11; rel err < 7e-6)
    const float s1 = LSCALE;
    const float s2 = 0.5f * s1 * s1;
    const float s3 = (1.0f / 6.0f) * s1 * s1 * s1;
    const ull C3 = pk2(s3, s3), C2 = pk2(s2, s2);
    const ull C1 = pk2(s1, s1), CONE = pk2(1.0f, 1.0f);

    // E/X/Y accumulators for 4 row-subsets (m-group x {r, r+8})
    ull E[2][2], X[2][2], Y[2][2];
    #pragma unroll
    for (int m = 0; m < 2; m++)
        #pragma unroll
        for (int q = 0; q < 2; q++) {
            E[m][q] = pk2(0.f, 0.f); X[m][q] = E[m][q]; Y[m][q] = E[m][q];
        }

    const int sl_base = h * 64 + 2 * (lane & 3);

    // Single accumulator set, refilled per jp after its EPI drains it
    int acc[4][2][2][4];

    // --- MMA block for column group jp of the tile in buffer Bbase ---
    auto MMAJ = [&](uint32_t Bbase, int jp) {
        #pragma unroll
        for (int m = 0; m < 2; m++)
            #pragma unroll
            for (int s = 0; s < 2; s++)
                #pragma unroll
                for (int q = 0; q < 4; q++) acc[jp][m][s][q] = 0;
        #pragma unroll
        for (int kk = 0; kk < 8; kk++) {
            uint32_t addr = Bbase + jp * 4096 + offk[kk];
            uint32_t b0, b1, b2, b3;
            ldmatrix_x4(b0, b1, b2, b3, addr);
            mma_s8(acc[jp][0][0], a[kk][0][0], a[kk][0][1], a[kk][0][2], a[kk][0][3], b0, b1);
            mma_s8(acc[jp][0][1], a[kk][0][0], a[kk][0][1], a[kk][0][2], a[kk][0][3], b2, b3);
            mma_s8(acc[jp][1][0], a[kk][1][0], a[kk][1][1], a[kk][1][2], a[kk][1][3], b0, b1);
            mma_s8(acc[jp][1][1], a[kk][1][0], a[kk][1][1], a[kk][1][2], a[kk][1][3], b2, b3);
        }
    };

    // Prologue MMA: tile 0, all jp (buffer 0)
    {
        const uint32_t Bb0 = sbase + SM_B + bRowOff;
        MMAJ(Bb0, 0); MMAJ(Bb0, 1); MMAJ(Bb0, 2); MMAJ(Bb0, 3);
    }

    for (int t = 0; t < NT; t++) {
        const bool last = (t == NT - 1);
        if (!last) {
            asm volatile("cp.async.wait_group 1;\n" ::);  // buffer t+1 resident
            __syncthreads();                              // visible to all; t-1 buffer free
        }
        if (t + 3 < NT) loadB(t + 3);
        else asm volatile("cp.async.commit_group;\n" ::);  // keep group ids aligned

        // Tile-t coordinate constants (for EPI of tile t)
        const int scol = t * TN;
        const int y0 = scol / GW;
        const int x0 = scol - y0 * GW;
        const int wrp = GW - x0;
        const float y0f = (float)y0, y1f = y0f + 1.f;
        const float xa = (float)x0, xb = (float)(x0 - GW);

        const uint32_t BbaseN =
            sbase + SM_B + (uint32_t)((t + 1) & (NBUF - 1)) * 32768u + bRowOff;

        // --- Epilogue for column group jp of tile t ---
        auto EPIJ = [&](int jp) {
            #pragma unroll
            for (int s = 0; s < 2; s++) {
                int j = jp * 2 + s;
                int sl0 = j * 8 + sl_base, sl1 = sl0 + 1;
                bool p0 = sl0 >= wrp, p1 = sl1 >= wrp;
                ull xp = pk2((p0 ? xb : xa) + (float)sl0, (p1 ? xb : xa) + (float)sl1);
                ull yp = pk2(p0 ? y1f : y0f, p1 ? y1f : y0f);
                #pragma unroll
                for (int m = 0; m < 2; m++) {
                    ull vlo = pk2(__int2float_rn(acc[jp][m][s][0]),
                                  __int2float_rn(acc[jp][m][s][1]));
                    ull vhi = pk2(__int2float_rn(acc[jp][m][s][2]),
                                  __int2float_rn(acc[jp][m][s][3]));

                    ull e = fma2(vlo, C3, C2);
                    e = fma2(vlo, e, C1);
                    e = fma2(vlo, e, CONE);
                    E[m][0] = add2(E[m][0], e);
                    X[m][0] = fma2(e, xp, X[m][0]);
                    Y[m][0] = fma2(e, yp, Y[m][0]);

                    ull f = fma2(vhi, C3, C2);
                    f = fma2(vhi, f, C1);
                    f = fma2(vhi, f, CONE);
                    E[m][1] = add2(E[m][1], f);
                    X[m][1] = fma2(f, xp, X[m][1]);
                    Y[m][1] = fma2(f, yp, Y[m][1]);
                }
            }
        };

        // Interleave: EPI of tile t fills issue slots under MMA of tile t+1
        EPIJ(0);
        if (!last) MMAJ(BbaseN, 0);
        EPIJ(1);
        if (!last) MMAJ(BbaseN, 1);
        EPIJ(2);
        if (!last) MMAJ(BbaseN, 2);
        EPIJ(3);
        if (!last) MMAJ(BbaseN, 3);
    }

    // Fold packed halves, reduce across lane quads, publish per-half partials
    float* part = (float*)(smem + SM_PART);
    #pragma unroll
    for (int m = 0; m < 2; m++) {
        #pragma unroll
        for (int q = 0; q < 2; q++) {
            float ea, eb, xa2, xb2, ya, yb;
            upk2(E[m][q], ea, eb); upk2(X[m][q], xa2, xb2); upk2(Y[m][q], ya, yb);
            float sE = ea + eb, sX = xa2 + xb2, sY = ya + yb;
            #pragma unroll
            for (int off = 1; off < 4; off <<= 1) {
                sE += __shfl_xor_sync(0xffffffffu, sE, off);
                sX += __shfl_xor_sync(0xffffffffu, sX, off);
                sY += __shfl_xor_sync(0xffffffffu, sY, off);
            }
            if ((lane & 3) == 0) {
                int row = wr + m * 16 + q * 8 + (lane >> 2);
                float* pp = part + (size_t)(h * 128 + row) * 3;
                pp[0] = sE; pp[1] = sX; pp[2] = sY;
            }
        }
    }
    __syncthreads();

    if (tid < 128) {
        const int row = tid;
        float sE = part[row * 3 + 0] + part[(128 + row) * 3 + 0];
        float sX = part[row * 3 + 1] + part[(128 + row) * 3 + 1];
        float sY = part[row * 3 + 2] + part[(128 + row) * 3 + 2];
        const int lq = rowBase + row;
        const int xq = lq % GW, yq = lq / GW;
        const bool border = (xq < 2) | (xq >= GW - 2) | (yq < 2) | (yq >= GW - 2);
        const float inv = 1.0f / sE;
        float* outb = out + (size_t)bat * 2 * L_DIM;
        outb[lq] = border ? 0.0f : (sX * inv - (float)xq);
        outb[L_DIM + lq] = border ? 0.0f : (sY * inv - (float)yq);
    }
}

// ---------------------------------------------------------------------------
extern "C" void kernel_launch(void* const* d_in, const int* in_sizes, int n_in,
                              void* d_out, int out_size) {
    (void)in_sizes; (void)n_in; (void)out_size;
    const float* feat0 = (const float*)d_in[0];
    const float* feat1 = (const float*)d_in[1];
    const float* Wm    = (const float*)d_in[2];
    const float* bias  = (const float*)d_in[3];
    float* out = (float*)d_out;

    cudaFuncSetAttribute(proj_kernel, cudaFuncAttributeMaxDynamicSharedMemorySize, 196608);
    cudaFuncSetAttribute(attn_kernel, cudaFuncAttributeMaxDynamicSharedMemorySize, SM_TOTAL);

    proj_kernel<<<dim3(NROWS / 128, 2), 256, 196608>>>(feat0, feat1, Wm, bias);
    attn_kernel<<<dim3(L_DIM / TM, 2), 256, SM_TOTAL>>>(out);
}

// round 10
// speedup vs baseline: 1.0898x; 1.0481x over previous
#include <cuda_runtime.h>
#include <cuda_bf16.h>
#include <cstdint>
#include <cstddef>

// Problem constants
#define L_DIM 9216          // 96*96
#define C_DIM 256
#define GW    96
#define NROWS (2 * L_DIM)   // B*L
// attn tiling
#define TM 128
#define TN 128
#define NT (L_DIM / TN)     // 72
#define NBUF 4

#define QSCALE 20.0f
// logits = dot_int / (QSCALE^2 * 16^3)
#define LSCALE (1.0f / (400.0f * 4096.0f))

// int8-quantized projected features (scratch)
__device__ __align__(128) uint8_t g_q0[NROWS * C_DIM];
__device__ __align__(128) uint8_t g_q1[NROWS * C_DIM];

typedef unsigned long long ull;

static __device__ __forceinline__ uint32_t smem_u32(const void* p) {
    return (uint32_t)__cvta_generic_to_shared(p);
}

// ---------------- f32x2 packed math ----------------
static __device__ __forceinline__ ull pk2(float a, float b) {
    ull r; asm("mov.b64 %0, {%1,%2};" : "=l"(r) : "f"(a), "f"(b)); return r;
}
static __device__ __forceinline__ void upk2(ull v, float& a, float& b) {
    asm("mov.b64 {%0,%1}, %2;" : "=f"(a), "=f"(b) : "l"(v));
}
static __device__ __forceinline__ ull fma2(ull a, ull b, ull c) {
    ull d; asm("fma.rn.f32x2 %0,%1,%2,%3;" : "=l"(d) : "l"(a), "l"(b), "l"(c)); return d;
}
static __device__ __forceinline__ ull add2(ull a, ull b) {
    ull d; asm("add.rn.f32x2 %0,%1,%2;" : "=l"(d) : "l"(a), "l"(b)); return d;
}

// ---------------- ldmatrix / mma ----------------
static __device__ __forceinline__ void ldmatrix_x4(uint32_t& r0, uint32_t& r1,
                                                   uint32_t& r2, uint32_t& r3,
                                                   uint32_t addr) {
    asm volatile("ldmatrix.sync.aligned.m8n8.x4.shared.b16 {%0,%1,%2,%3}, [%4];\n"
                 : "=r"(r0), "=r"(r1), "=r"(r2), "=r"(r3) : "r"(addr));
}
static __device__ __forceinline__ void mma16816(float* c, uint32_t a0, uint32_t a1,
                                                uint32_t a2, uint32_t a3, uint32_t b0,
                                                uint32_t b1) {
    asm volatile(
        "mma.sync.aligned.m16n8k16.row.col.f32.bf16.bf16.f32 "
        "{%0,%1,%2,%3}, {%4,%5,%6,%7}, {%8,%9}, {%0,%1,%2,%3};\n"
        : "+f"(c[0]), "+f"(c[1]), "+f"(c[2]), "+f"(c[3])
        : "r"(a0), "r"(a1), "r"(a2), "r"(a3), "r"(b0), "r"(b1));
}
static __device__ __forceinline__ void mma_s8(int* c, uint32_t a0, uint32_t a1,
                                              uint32_t a2, uint32_t a3, uint32_t b0,
                                              uint32_t b1) {
    asm volatile(
        "mma.sync.aligned.m16n8k32.row.col.s32.s8.s8.s32 "
        "{%0,%1,%2,%3}, {%4,%5,%6,%7}, {%8,%9}, {%0,%1,%2,%3};\n"
        : "+r"(c[0]), "+r"(c[1]), "+r"(c[2]), "+r"(c[3])
        : "r"(a0), "r"(a1), "r"(a2), "r"(a3), "r"(b0), "r"(b1));
}

// Swizzle for 512B rows (bf16 tiles)
static __device__ __forceinline__ int sw_off(int r, int c) {
    return r * 512 + (((c) ^ (r & 7)) << 4);
}
// Swizzle for 256B rows (int8 tiles): 16 chunks of 16B
static __device__ __forceinline__ int swb(int r, int c) {
    return r * 256 + ((c & 8) << 4) + (((c ^ r) & 7) << 4);
}

// ===========================================================================
// Projection kernel: f = feat @ W^T + b  (bf16 mma) -> int8 (x QSCALE)
// ===========================================================================
__global__ void __launch_bounds__(256) proj_kernel(const float* __restrict__ feat0,
                                                   const float* __restrict__ feat1,
                                                   const float* __restrict__ Wm,
                                                   const float* __restrict__ bias) {
    extern __shared__ char smem[];
    char* As = smem;            // 64 KB
    char* Ws = smem + 65536;    // 128 KB (all 256 rows of W)

    const int tid = threadIdx.x;
    const int warp = tid >> 5, lane = tid & 31;
    const bool is1 = (blockIdx.y != 0);
    const float* feat = is1 ? feat1 : feat0;
    uint8_t* outp = is1 ? g_q1 : g_q0;
    const int rowBase = blockIdx.x * 128;

    #pragma unroll
    for (int i = tid; i < 128 * 32; i += 256) {
        int r = i >> 5, c = i & 31;
        const float* src = feat + (size_t)(rowBase + r) * C_DIM + c * 8;
        float4 v0 = *(const float4*)(src);
        float4 v1 = *(const float4*)(src + 4);
        __nv_bfloat162 p0 = __floats2bfloat162_rn(v0.x, v0.y);
        __nv_bfloat162 p1 = __floats2bfloat162_rn(v0.z, v0.w);
        __nv_bfloat162 p2 = __floats2bfloat162_rn(v1.x, v1.y);
        __nv_bfloat162 p3 = __floats2bfloat162_rn(v1.z, v1.w);
        uint4 u;
        u.x = *(uint32_t*)&p0; u.y = *(uint32_t*)&p1;
        u.z = *(uint32_t*)&p2; u.w = *(uint32_t*)&p3;
        *(uint4*)(As + sw_off(r, c)) = u;
    }
    #pragma unroll
    for (int i = tid; i < 256 * 32; i += 256) {
        int r = i >> 5, c = i & 31;
        const float* src = Wm + (size_t)r * C_DIM + c * 8;
        float4 v0 = *(const float4*)(src);
        float4 v1 = *(const float4*)(src + 4);
        __nv_bfloat162 p0 = __floats2bfloat162_rn(v0.x, v0.y);
        __nv_bfloat162 p1 = __floats2bfloat162_rn(v0.z, v0.w);
        __nv_bfloat162 p2 = __floats2bfloat162_rn(v1.x, v1.y);
        __nv_bfloat162 p3 = __floats2bfloat162_rn(v1.z, v1.w);
        uint4 u;
        u.x = *(uint32_t*)&p0; u.y = *(uint32_t*)&p1;
        u.z = *(uint32_t*)&p2; u.w = *(uint32_t*)&p3;
        *(uint4*)(Ws + sw_off(r, c)) = u;
    }
    __syncthreads();

    uint32_t a[16][4];
    const int wr = warp * 16;
    const int aR = wr + (lane & 7) + (lane & 8);
    const uint32_t aRowBase = smem_u32(As) + aR * 512;
    const int aXor = aR & 7;
    #pragma unroll
    for (int kk = 0; kk < 16; kk++) {
        int chunk = kk * 2 + (lane >> 4);
        ldmatrix_x4(a[kk][0], a[kk][1], a[kk][2], a[kk][3],
                    aRowBase + ((chunk ^ aXor) << 4));
    }

    const int bR = (lane & 7) + ((lane & 16) >> 1);
    const int bChunkOff = (lane >> 3) & 1;
    const uint32_t wsBase = smem_u32(Ws);

    #pragma unroll 1
    for (int nt = 0; nt < 4; nt++) {
        float acc[8][4];
        #pragma unroll
        for (int j = 0; j < 8; j++)
            #pragma unroll
            for (int q = 0; q < 4; q++) acc[j][q] = 0.0f;

        #pragma unroll
        for (int kk = 0; kk < 16; kk++) {
            #pragma unroll
            for (int jp = 0; jp < 4; jp++) {
                int R = nt * 64 + jp * 16 + bR;
                uint32_t addr = wsBase + R * 512 +
                                (((kk * 2 + bChunkOff) ^ (R & 7)) << 4);
                uint32_t b0, b1, b2, b3;
                ldmatrix_x4(b0, b1, b2, b3, addr);
                mma16816(acc[jp * 2],     a[kk][0], a[kk][1], a[kk][2], a[kk][3], b0, b1);
                mma16816(acc[jp * 2 + 1], a[kk][0], a[kk][1], a[kk][2], a[kk][3], b2, b3);
            }
        }

        int r0 = rowBase + wr + (lane >> 2);
        #pragma unroll
        for (int j = 0; j < 8; j++) {
            int col = nt * 64 + j * 8 + 2 * (lane & 3);
            float bb0 = bias[col], bb1 = bias[col + 1];
            int i0 = __float2int_rn(fminf(fmaxf((acc[j][0] + bb0) * QSCALE, -127.f), 127.f));
            int i1 = __float2int_rn(fminf(fmaxf((acc[j][1] + bb1) * QSCALE, -127.f), 127.f));
            int i2 = __float2int_rn(fminf(fmaxf((acc[j][2] + bb0) * QSCALE, -127.f), 127.f));
            int i3 = __float2int_rn(fminf(fmaxf((acc[j][3] + bb1) * QSCALE, -127.f), 127.f));
            uint16_t lo = (uint16_t)((i0 & 0xff) | ((i1 & 0xff) << 8));
            uint16_t hi = (uint16_t)((i2 & 0xff) | ((i3 & 0xff) << 8));
            *(uint16_t*)(outp + (size_t)r0 * C_DIM + col) = lo;
            *(uint16_t*)(outp + (size_t)(r0 + 8) * C_DIM + col) = hi;
        }
    }
}

// ===========================================================================
// Attention kernel: int8 mma, 256 threads, warp tile M=32 x N=64.
// Instruction-granular software pipeline (ring, one-jp phase shift):
//   body t, block jp:  MMA_{t+1}(jp) k-steps interleaved with
//                      EPI_t(jp+1) chunks (block 3 carries EPI_{t+1}(0)).
// EPI reads accumulators produced >= 1 block earlier (retired); the FFMA2/I2F
// stream fills the issue slots the QMMA stream leaves open WITHIN one warp.
// ===========================================================================
#define SM_A 0
#define SM_B 32768
#define SM_PART (32768 + NBUF * 32768)              // 163840
#define SM_TOTAL (SM_PART + 2 * 128 * 3 * 4)        // +3072

struct Coord {
    int wrp;
    float y0f, y1f, xa, xb;
};

__global__ void __launch_bounds__(256, 1) attn_kernel(float* __restrict__ out) {
    extern __shared__ char smem[];
    const uint32_t sbase = smem_u32(smem);
    const int tid = threadIdx.x;
    const int warp = tid >> 5, lane = tid & 31;
    const int g = warp >> 1;      // row group 0..3 (32 rows each)
    const int h = warp & 1;       // col half 0..1
    const int bat = blockIdx.y;
    const uint8_t* f0 = g_q0 + (size_t)bat * L_DIM * C_DIM;
    const uint8_t* f1 = g_q1 + (size_t)bat * L_DIM * C_DIM;
    const int rowBase = blockIdx.x * TM;

    auto loadB = [&](int t) {
        const uint8_t* src = f1 + (size_t)t * TN * C_DIM;
        uint32_t Bb = sbase + SM_B + (uint32_t)(t & (NBUF - 1)) * 32768u;
        #pragma unroll
        for (int k = 0; k < 8; k++) {
            int i = k * 256 + tid;
            int r = i >> 4, c = i & 15;
            uint32_t dst = Bb + swb(r, c);
            const void* gp = (const void*)(src + r * C_DIM + c * 16);
            asm volatile("cp.async.cg.shared.global [%0], [%1], 16;\n" ::"r"(dst), "l"(gp));
        }
        asm volatile("cp.async.commit_group;\n" ::);
    };

    // Prologue: group0 = A tile + B0; groups 1,2 = B1,B2
    #pragma unroll
    for (int k = 0; k < 8; k++) {
        int i = k * 256 + tid;
        int r = i >> 4, c = i & 15;
        uint32_t dst = sbase + SM_A + swb(r, c);
        const void* gp = (const void*)(f0 + (size_t)(rowBase + r) * C_DIM + c * 16);
        asm volatile("cp.async.cg.shared.global [%0], [%1], 16;\n" ::"r"(dst), "l"(gp));
    }
    loadB(0);
    loadB(1);
    loadB(2);

    asm volatile("cp.async.wait_group 2;\n" ::);  // A + B0 resident
    __syncthreads();

    // Hoist A fragments: 8 k-steps x 2 m-groups x 4 regs (rows g*32..+32)
    uint32_t a[8][2][4];
    const int wr = g * 32;
    #pragma unroll
    for (int m = 0; m < 2; m++) {
        const int aR = wr + m * 16 + (lane & 7) + (lane & 8);
        const uint32_t aRowBase = sbase + SM_A + aR * 256;
        #pragma unroll
        for (int kk = 0; kk < 8; kk++) {
            int c = kk * 2 + (lane >> 4);
            ldmatrix_x4(a[kk][m][0], a[kk][m][1], a[kk][m][2], a[kk][m][3],
                        aRowBase + ((c & 8) << 4) + (((c ^ aR) & 7) << 4));
        }
    }

    // B ldmatrix addressing: hoist swizzle offsets (lane-constant)
    const int bRlo = (lane & 7) + ((lane >> 4) << 3);
    const int bCk = (lane >> 3) & 1;
    const int r7 = bRlo & 7;
    uint32_t offk[8];
    #pragma unroll
    for (int kk = 0; kk < 8; kk++) {
        int c = kk * 2 + bCk;
        offk[kk] = (uint32_t)(((c & 8) << 4) + (((c ^ r7) & 7) << 4));
    }
    const uint32_t bRowOff = (uint32_t)((h * 64 + bRlo) * 256);

    // exp(LSCALE * v), degree-3 Taylor (|LSCALE*v| <= ~0.11; rel err < 7e-6)
    const float s1 = LSCALE;
    const float s2 = 0.5f * s1 * s1;
    const float s3 = (1.0f / 6.0f) * s1 * s1 * s1;
    const ull C3 = pk2(s3, s3), C2 = pk2(s2, s2);
    const ull C1 = pk2(s1, s1), CONE = pk2(1.0f, 1.0f);

    // E/X/Y accumulators for 4 row-subsets (m-group x {r, r+8})
    ull E[2][2], X[2][2], Y[2][2];
    #pragma unroll
    for (int m = 0; m < 2; m++)
        #pragma unroll
        for (int q = 0; q < 2; q++) {
            E[m][q] = pk2(0.f, 0.f); X[m][q] = E[m][q]; Y[m][q] = E[m][q];
        }

    const int sl_base = h * 64 + 2 * (lane & 3);

    // Single accumulator set, refilled per jp after its EPI drains it
    int acc[4][2][2][4];

    auto ZERO = [&](int jp) {
        #pragma unroll
        for (int m = 0; m < 2; m++)
            #pragma unroll
            for (int s = 0; s < 2; s++)
                #pragma unroll
                for (int q = 0; q < 4; q++) acc[jp][m][s][q] = 0;
    };
    // One MMA k-step for column group jp against buffer Bbase
    auto MMAK = [&](uint32_t Bbase, int jp, int kk) {
        uint32_t addr = Bbase + jp * 4096 + offk[kk];
        uint32_t b0, b1, b2, b3;
        ldmatrix_x4(b0, b1, b2, b3, addr);
        mma_s8(acc[jp][0][0], a[kk][0][0], a[kk][0][1], a[kk][0][2], a[kk][0][3], b0, b1);
        mma_s8(acc[jp][0][1], a[kk][0][0], a[kk][0][1], a[kk][0][2], a[kk][0][3], b2, b3);
        mma_s8(acc[jp][1][0], a[kk][1][0], a[kk][1][1], a[kk][1][2], a[kk][1][3], b0, b1);
        mma_s8(acc[jp][1][1], a[kk][1][0], a[kk][1][1], a[kk][1][2], a[kk][1][3], b2, b3);
    };
    auto mkCoord = [&](int t) {
        Coord c;
        int scol = t * TN;
        int y0 = scol / GW;
        int x0 = scol - y0 * GW;
        c.wrp = GW - x0;
        c.y0f = (float)y0; c.y1f = c.y0f + 1.f;
        c.xa = (float)x0; c.xb = (float)(x0 - GW);
        return c;
    };
    // One EPI s-chunk (16 values across 2 m-groups) for group jp with coords ct
    auto EPIS = [&](const Coord& ct, int jp, int s) {
        int j = jp * 2 + s;
        int sl0 = j * 8 + sl_base, sl1 = sl0 + 1;
        bool p0 = sl0 >= ct.wrp, p1 = sl1 >= ct.wrp;
        ull xp = pk2((p0 ? ct.xb : ct.xa) + (float)sl0, (p1 ? ct.xb : ct.xa) + (float)sl1);
        ull yp = pk2(p0 ? ct.y1f : ct.y0f, p1 ? ct.y1f : ct.y0f);
        #pragma unroll
        for (int m = 0; m < 2; m++) {
            ull vlo = pk2(__int2float_rn(acc[jp][m][s][0]), __int2float_rn(acc[jp][m][s][1]));
            ull vhi = pk2(__int2float_rn(acc[jp][m][s][2]), __int2float_rn(acc[jp][m][s][3]));

            ull e = fma2(vlo, C3, C2);
            e = fma2(vlo, e, C1);
            e = fma2(vlo, e, CONE);
            E[m][0] = add2(E[m][0], e);
            X[m][0] = fma2(e, xp, X[m][0]);
            Y[m][0] = fma2(e, yp, Y[m][0]);

            ull f = fma2(vhi, C3, C2);
            f = fma2(vhi, f, C1);
            f = fma2(vhi, f, CONE);
            E[m][1] = add2(E[m][1], f);
            X[m][1] = fma2(f, xp, X[m][1]);
            Y[m][1] = fma2(f, yp, Y[m][1]);
        }
    };

    // Prologue MMA: tile 0, all jp (buffer 0); then EPI_0(0) (unoverlapped)
    {
        const uint32_t Bb0 = sbase + SM_B + bRowOff;
        #pragma unroll
        for (int jp = 0; jp < 4; jp++) {
            ZERO(jp);
            #pragma unroll
            for (int kk = 0; kk < 8; kk++) MMAK(Bb0, jp, kk);
        }
        Coord c0 = mkCoord(0);
        EPIS(c0, 0, 0);
        EPIS(c0, 0, 1);
    }

    for (int t = 0; t < NT; t++) {
        const bool last = (t == NT - 1);
        if (!last) {
            asm volatile("cp.async.wait_group 1;\n" ::);  // buffer t+1 resident
            __syncthreads();                              // visible to all; old buffer free
        }
        if (t + 3 < NT) loadB(t + 3);
        else asm volatile("cp.async.commit_group;\n" ::);  // keep group ids aligned

        const Coord cT = mkCoord(t);
        const Coord cN = mkCoord(t + 1 < NT ? t + 1 : t);  // dummy when last

        const uint32_t BbaseN =
            sbase + SM_B + (uint32_t)((t + 1) & (NBUF - 1)) * 32768u + bRowOff;

        if (!last) {
            // Block jp: MMA_{t+1}(jp) k-steps interleaved with EPI chunks of
            // EPI_t(jp+1) (block 3: EPI_{t+1}(0), produced by block 0 above).
            // --- jp = 0, EPI target (t, 1) ---
            ZERO(0);
            MMAK(BbaseN, 0, 0); MMAK(BbaseN, 0, 1); MMAK(BbaseN, 0, 2);
            EPIS(cT, 1, 0);
            MMAK(BbaseN, 0, 3); MMAK(BbaseN, 0, 4); MMAK(BbaseN, 0, 5);
            EPIS(cT, 1, 1);
            MMAK(BbaseN, 0, 6); MMAK(BbaseN, 0, 7);
            // --- jp = 1, EPI target (t, 2) ---
            ZERO(1);
            MMAK(BbaseN, 1, 0); MMAK(BbaseN, 1, 1); MMAK(BbaseN, 1, 2);
            EPIS(cT, 2, 0);
            MMAK(BbaseN, 1, 3); MMAK(BbaseN, 1, 4); MMAK(BbaseN, 1, 5);
            EPIS(cT, 2, 1);
            MMAK(BbaseN, 1, 6); MMAK(BbaseN, 1, 7);
            // --- jp = 2, EPI target (t, 3) ---
            ZERO(2);
            MMAK(BbaseN, 2, 0); MMAK(BbaseN, 2, 1); MMAK(BbaseN, 2, 2);
            EPIS(cT, 3, 0);
            MMAK(BbaseN, 2, 3); MMAK(BbaseN, 2, 4); MMAK(BbaseN, 2, 5);
            EPIS(cT, 3, 1);
            MMAK(BbaseN, 2, 6); MMAK(BbaseN, 2, 7);
            // --- jp = 3, EPI target (t+1, 0) ---
            ZERO(3);
            MMAK(BbaseN, 3, 0); MMAK(BbaseN, 3, 1); MMAK(BbaseN, 3, 2);
            EPIS(cN, 0, 0);
            MMAK(BbaseN, 3, 3); MMAK(BbaseN, 3, 4); MMAK(BbaseN, 3, 5);
            EPIS(cN, 0, 1);
            MMAK(BbaseN, 3, 6); MMAK(BbaseN, 3, 7);
        } else {
            // Tail: finish EPI of the last tile (groups 1..3; group 0 was
            // handled by the previous body's jp=3 block)
            EPIS(cT, 1, 0); EPIS(cT, 1, 1);
            EPIS(cT, 2, 0); EPIS(cT, 2, 1);
            EPIS(cT, 3, 0); EPIS(cT, 3, 1);
        }
    }

    // Fold packed halves, reduce across lane quads, publish per-half partials
    float* part = (float*)(smem + SM_PART);
    #pragma unroll
    for (int m = 0; m < 2; m++) {
        #pragma unroll
        for (int q = 0; q < 2; q++) {
            float ea, eb, xa2, xb2, ya, yb;
            upk2(E[m][q], ea, eb); upk2(X[m][q], xa2, xb2); upk2(Y[m][q], ya, yb);
            float sE = ea + eb, sX = xa2 + xb2, sY = ya + yb;
            #pragma unroll
            for (int off = 1; off < 4; off <<= 1) {
                sE += __shfl_xor_sync(0xffffffffu, sE, off);
                sX += __shfl_xor_sync(0xffffffffu, sX, off);
                sY += __shfl_xor_sync(0xffffffffu, sY, off);
            }
            if ((lane & 3) == 0) {
                int row = wr + m * 16 + q * 8 + (lane >> 2);
                float* pp = part + (size_t)(h * 128 + row) * 3;
                pp[0] = sE; pp[1] = sX; pp[2] = sY;
            }
        }
    }
    __syncthreads();

    if (tid < 128) {
        const int row = tid;
        float sE = part[row * 3 + 0] + part[(128 + row) * 3 + 0];
        float sX = part[row * 3 + 1] + part[(128 + row) * 3 + 1];
        float sY = part[row * 3 + 2] + part[(128 + row) * 3 + 2];
        const int lq = rowBase + row;
        const int xq = lq % GW, yq = lq / GW;
        const bool border = (xq < 2) | (xq >= GW - 2) | (yq < 2) | (yq >= GW - 2);
        const float inv = 1.0f / sE;
        float* outb = out + (size_t)bat * 2 * L_DIM;
        outb[lq] = border ? 0.0f : (sX * inv - (float)xq);
        outb[L_DIM + lq] = border ? 0.0f : (sY * inv - (float)yq);
    }
}

// ---------------------------------------------------------------------------
extern "C" void kernel_launch(void* const* d_in, const int* in_sizes, int n_in,
                              void* d_out, int out_size) {
    (void)in_sizes; (void)n_in; (void)out_size;
    const float* feat0 = (const float*)d_in[0];
    const float* feat1 = (const float*)d_in[1];
    const float* Wm    = (const float*)d_in[2];
    const float* bias  = (const float*)d_in[3];
    float* out = (float*)d_out;

    cudaFuncSetAttribute(proj_kernel, cudaFuncAttributeMaxDynamicSharedMemorySize, 196608);
    cudaFuncSetAttribute(attn_kernel, cudaFuncAttributeMaxDynamicSharedMemorySize, SM_TOTAL);

    proj_kernel<<<dim3(NROWS / 128, 2), 256, 196608>>>(feat0, feat1, Wm, bias);
    attn_kernel<<<dim3(L_DIM / TM, 2), 256, SM_TOTAL>>>(out);
}